// round 4
// baseline (speedup 1.0000x reference)
#include <cuda_runtime.h>
#include <math.h>

#define T_  128
#define B_  32
#define I_  128
#define H_  128
#define R_  100
#define O_  64
#define RH_ (R_*H_)       // 12800
#define COLS_ (H_*B_)     // 4096  (k,b) flat columns per region

typedef unsigned long long u64;

// Scratch (static device globals)
static __device__ float g_inp[(size_t)T_*R_*B_*H_];    // [T][R][b][g]
static __device__ float g_Hbr[(size_t)T_*B_*RH_];      // [T][b][r*H+g]  (for out_kernel)
static __device__ float g_Hkb[(size_t)T_*R_*COLS_];    // [T][r][g*32+b] (for phases)
static __device__ float g_msg[(size_t)R_*COLS_];       // [r][g*32+b]
static __device__ unsigned g_arrive;                   // grid-barrier counter

// ---- packed f32x2 helpers (sm_103a) ----
__device__ __forceinline__ u64 pk2(float lo, float hi){
    u64 r; asm("mov.b64 %0, {%1,%2};" : "=l"(r) : "f"(lo), "f"(hi)); return r;
}
__device__ __forceinline__ void up2(u64 v, float& lo, float& hi){
    asm("mov.b64 {%0,%1}, %2;" : "=f"(lo), "=f"(hi) : "l"(v));
}
__device__ __forceinline__ u64 fma2(u64 a, u64 b, u64 c){
    u64 d; asm("fma.rn.f32x2 %0, %1, %2, %3;" : "=l"(d) : "l"(a), "l"(b), "l"(c)); return d;
}

// ============================================================================
// Kernel 1: inp[t,r,b,g] = sum_i x[t,b,i]*W_ih[r,i,g] + bias[r,g]
// Thread owns 2 g-cols x 4 b-pairs. Also resets the grid-barrier counter.
// ============================================================================
__global__ __launch_bounds__(256) void inp_kernel(const float* __restrict__ x,
                                                  const float* __restrict__ W_ih,
                                                  const float* __restrict__ bias){
    if (blockIdx.x == 0 && blockIdx.y == 0 && threadIdx.x == 0) g_arrive = 0u;

    int r = blockIdx.x, t = blockIdx.y;
    __shared__ u64 xs[16][128];
    const float* xt = x + (size_t)t*B_*I_;
    for (int idx = threadIdx.x; idx < B_*I_; idx += 256){
        int b = idx >> 7, k = idx & 127;
        reinterpret_cast<float*>(&xs[b>>1][k])[b&1] = xt[idx];
    }
    __syncthreads();

    int gg = threadIdx.x & 63, quad = threadIdx.x >> 6;
    float bva = bias[r*H_ + gg], bvb = bias[r*H_ + gg + 64];
    u64 acc[8];
#pragma unroll
    for (int p=0;p<4;p++){ acc[p*2+0] = pk2(bva,bva); acc[p*2+1] = pk2(bvb,bvb); }

    const float* W = W_ih + (size_t)r*I_*H_;
#pragma unroll 4
    for (int k=0;k<I_;k++){
        float wa = W[(size_t)k*H_ + gg];
        float wb = W[(size_t)k*H_ + gg + 64];
        u64 wad = pk2(wa,wa), wbd = pk2(wb,wb);
#pragma unroll
        for (int p=0;p<4;p++){
            u64 xv = xs[quad*4+p][k];
            acc[p*2+0] = fma2(xv, wad, acc[p*2+0]);
            acc[p*2+1] = fma2(xv, wbd, acc[p*2+1]);
        }
    }
    float* op = g_inp + (size_t)(t*R_ + r)*B_*H_;
#pragma unroll
    for (int p=0;p<4;p++){
        int b0 = quad*8 + 2*p;
#pragma unroll
        for (int e=0;e<2;e++){
            float lo, hi; up2(acc[p*2+e], lo, hi);
            op[b0*H_     + gg + e*64] = lo;
            op[(b0+1)*H_ + gg + e*64] = hi;
        }
    }
}

// ============================================================================
// Persistent recurrent kernel (runs steps [t0,t1)): grid = 100, 512 threads.
// ============================================================================
#define SM_W1   0
#define SM_W2   16384
#define SM_C    32768
#define SM_HT   42768          // 4096 floats [k*32+b]
#define SM_MT   46864          // 4096 floats
#define SM_FLOATS 50960        // 203840 bytes

__device__ __forceinline__ void gbar(unsigned target){
    __threadfence();
    __syncthreads();
    if (threadIdx.x == 0){
        atomicAdd(&g_arrive, 1u);
        volatile unsigned* va = &g_arrive;
        while (*va < target) { }
    }
    __syncthreads();
}

// phase A body: NJP j-pairs, 2 cols (c, c+32) within the strip
template<int NJP>
__device__ __forceinline__ void msg_body(const float* __restrict__ Cs,
                                         const float* __restrict__ Hs,
                                         int c, int jp0, int col0){
    u64 acc[NJP*2];
#pragma unroll
    for (int j=0;j<NJP*2;j++) acc[j] = 0ull;
#pragma unroll 2
    for (int i=0;i<R_;i++){
        float h0 = Hs[i*64 + c], h1 = Hs[i*64 + c + 32];
        u64 h0d = pk2(h0,h0), h1d = pk2(h1,h1);
        const float* Cr = Cs + i*R_ + jp0*2;
#pragma unroll
        for (int j=0;j<NJP;j++){
            u64 Cv = *reinterpret_cast<const u64*>(Cr + 2*j);   // {C[i,j],C[i,j+1]}
            acc[j*2+0] = fma2(Cv, h0d, acc[j*2+0]);
            acc[j*2+1] = fma2(Cv, h1d, acc[j*2+1]);
        }
    }
#pragma unroll
    for (int j=0;j<NJP;j++){
        int jj = (jp0 + j)*2;
#pragma unroll
        for (int e=0;e<2;e++){
            float lo, hi; up2(acc[j*2+e], lo, hi);
            int col = col0 + c + e*32;
            __stcg(&g_msg[(size_t)jj*COLS_     + col], lo);
            __stcg(&g_msg[(size_t)(jj+1)*COLS_ + col], hi);
        }
    }
}

__global__ __launch_bounds__(512,1) void rnn_persist(const float* __restrict__ W_hh,
                                                     const float* __restrict__ W_rhh,
                                                     const float* __restrict__ C,
                                                     int t0, int t1, unsigned bars0){
    extern __shared__ float sm[];
    float* w1 = sm + SM_W1;
    float* w2 = sm + SM_W2;
    float* Cs = sm + SM_C;
    float* hT = sm + SM_HT;
    float* mT = sm + SM_MT;
    float* Hs = hT;                       // phase-A overlay (6400 floats)

    const int r = blockIdx.x, tid = threadIdx.x;

    // stage region weights + connectome
    {
        const float4* a  = reinterpret_cast<const float4*>(W_hh  + (size_t)r*H_*H_);
        const float4* bb = reinterpret_cast<const float4*>(W_rhh + (size_t)r*H_*H_);
        float4* d1 = reinterpret_cast<float4*>(w1);
        float4* d2 = reinterpret_cast<float4*>(w2);
        for (int i=tid;i<4096;i+=512){ d1[i]=a[i]; d2[i]=bb[i]; }
        const float4* c4 = reinterpret_cast<const float4*>(C);
        float4* dc = reinterpret_cast<float4*>(Cs);
        for (int i=tid;i<2500;i+=512) dc[i]=c4[i];
    }

    // phase-B mapping: gg -> g-cols {gg, gg+64}; bq -> b0..b0+3 (2 pairs)
    const int gg = tid & 63;
    const int bq = tid >> 6;
    const int b0 = bq*4;
    // phase-A mapping
    const int c  = tid & 31;
    const int jg = tid >> 5;
    const int jp0 = (jg<2)? jg*4 : 8 + (jg-2)*3;

    unsigned bars = bars0;

    for (int t = t0; t < t1; t++){
        // ---------------- phase A: msg strips (blocks 0..63) ----------------
        if (t > 0){
            if (r < 64){
                const int col0 = r*64;
                const float* Hp = g_Hkb + (size_t)(t-1)*R_*COLS_ + col0;
                float4* Hs4 = reinterpret_cast<float4*>(Hs);
                for (int idx=tid; idx<1600; idx+=512){
                    int i = idx >> 4, c4i = idx & 15;
                    Hs4[idx] = __ldcg(reinterpret_cast<const float4*>(Hp + (size_t)i*COLS_) + c4i);
                }
                __syncthreads();
                if (jg < 2) msg_body<4>(Cs, Hs, c, jp0, col0);
                else        msg_body<3>(Cs, Hs, c, jp0, col0);
            }
            gbar(++bars * (unsigned)R_);
        }

        // ---------------- phase B ----------------
        u64 acc[4];
        {
            const float* ip = g_inp + ((size_t)t*R_ + r)*B_*H_;
#pragma unroll
            for (int pp=0;pp<2;pp++){
#pragma unroll
                for (int e=0;e<2;e++){
                    int g = gg + e*64, b = b0 + 2*pp;
                    acc[pp*2+e] = pk2(ip[b*H_ + g], ip[(b+1)*H_ + g]);
                }
            }
        }
        if (t > 0){
            const float4* Hp4 = reinterpret_cast<const float4*>(g_Hkb + ((size_t)(t-1)*R_ + r)*COLS_);
            const float4* Mp4 = reinterpret_cast<const float4*>(g_msg + (size_t)r*COLS_);
            float4* hT4 = reinterpret_cast<float4*>(hT);
            float4* mT4 = reinterpret_cast<float4*>(mT);
            for (int i=tid;i<1024;i+=512){ hT4[i] = __ldcg(Hp4+i); mT4[i] = __ldcg(Mp4+i); }
            __syncthreads();
#pragma unroll 4
            for (int k=0;k<H_;k++){
                float w1a = w1[k*H_ + gg], w1b = w1[k*H_ + gg + 64];
                float w2a = w2[k*H_ + gg], w2b = w2[k*H_ + gg + 64];
                u64 w1ad = pk2(w1a,w1a), w1bd = pk2(w1b,w1b);
                u64 w2ad = pk2(w2a,w2a), w2bd = pk2(w2b,w2b);
                ulonglong2 hA = *reinterpret_cast<const ulonglong2*>(hT + k*32 + b0);
                ulonglong2 mA = *reinterpret_cast<const ulonglong2*>(mT + k*32 + b0);
                acc[0] = fma2(hA.x, w1ad, acc[0]);  acc[0] = fma2(mA.x, w2ad, acc[0]);
                acc[1] = fma2(hA.x, w1bd, acc[1]);  acc[1] = fma2(mA.x, w2bd, acc[1]);
                acc[2] = fma2(hA.y, w1ad, acc[2]);  acc[2] = fma2(mA.y, w2ad, acc[2]);
                acc[3] = fma2(hA.y, w1bd, acc[3]);  acc[3] = fma2(mA.y, w2bd, acc[3]);
            }
            __syncthreads();   // hT/mT (and Hs overlay) free for next phase A
        }
        {
            float* Hbr = g_Hbr + (size_t)t*B_*RH_ + (size_t)r*H_;
            float* Hkb = g_Hkb + ((size_t)t*R_ + r)*COLS_;
#pragma unroll
            for (int pp=0;pp<2;pp++){
#pragma unroll
                for (int e=0;e<2;e++){
                    float lo, hi; up2(acc[pp*2+e], lo, hi);
                    float tl = tanhf(lo), th = tanhf(hi);
                    int g = gg + e*64, b = b0 + 2*pp;
                    __stcg(Hbr + (size_t)b*RH_     + g, tl);
                    __stcg(Hbr + (size_t)(b+1)*RH_ + g, th);
                    float2 pr = make_float2(tl, th);
                    __stcg(reinterpret_cast<float2*>(Hkb + g*32 + b), pr);
                }
            }
        }
        if (t < t1-1) gbar(++bars * (unsigned)R_);
    }
}

// ============================================================================
// Kernel 3: out[t,b,o] = H[t][b][:] @ W_out + b_out   grid (T,2), 128 thr
// ============================================================================
__global__ __launch_bounds__(128) void out_kernel(const float* __restrict__ W_out,
                                                  const float* __restrict__ b_out,
                                                  float* __restrict__ out){
    int t = blockIdx.x, bh = blockIdx.y;
    __shared__ u64 hsh[128][9];
    int tid = threadIdx.x;
    int og = tid & 15, rp = tid >> 4;
    int o0 = og*4;
    u64 acc[4];
    {
        const u64* bo = reinterpret_cast<const u64*>(b_out + o0);
        acc[0]=bo[0]; acc[1]=bo[1]; acc[2]=bo[0]; acc[3]=bo[1];
    }
    const float* Hb = g_Hbr + (size_t)t*B_*RH_ + (size_t)(bh*16)*RH_;
    for (int kt=0; kt<RH_/128; kt++){
        __syncthreads();
        for (int idx = tid; idx < 16*128; idx += 128){
            int b = idx >> 7, kk = idx & 127;
            reinterpret_cast<float*>(&hsh[kk][b>>1])[b&1] = Hb[(size_t)b*RH_ + kt*128 + kk];
        }
        __syncthreads();
#pragma unroll 4
        for (int kk=0; kk<128; kk++){
            int k = kt*128 + kk;
            ulonglong2 w = *reinterpret_cast<const ulonglong2*>(W_out + (size_t)k*O_ + o0);
            u64 hp = hsh[kk][rp];
            float h0, h1; up2(hp, h0, h1);
            u64 h0d = pk2(h0,h0), h1d = pk2(h1,h1);
            acc[0] = fma2(w.x, h0d, acc[0]);  acc[1] = fma2(w.y, h0d, acc[1]);
            acc[2] = fma2(w.x, h1d, acc[2]);  acc[3] = fma2(w.y, h1d, acc[3]);
        }
    }
    u64* op = reinterpret_cast<u64*>(out);
    int row0 = bh*16 + rp*2;
    size_t base0 = ((size_t)(t*B_ + row0  )*O_ + o0) >> 1;
    size_t base1 = ((size_t)(t*B_ + row0+1)*O_ + o0) >> 1;
    op[base0] = acc[0];  op[base0+1] = acc[1];
    op[base1] = acc[2];  op[base1+1] = acc[3];
}

// ============================================================================
// Launch: inp, 4x persistent chunks of 32 steps, out.
// ============================================================================
extern "C" void kernel_launch(void* const* d_in, const int* in_sizes, int n_in,
                              void* d_out, int out_size){
    const float* x     = (const float*)d_in[0];
    const float* C     = (const float*)d_in[1];
    const float* W_ih  = (const float*)d_in[2];
    const float* W_hh  = (const float*)d_in[3];
    const float* W_rhh = (const float*)d_in[4];
    const float* bias  = (const float*)d_in[5];
    const float* W_out = (const float*)d_in[6];
    const float* b_out = (const float*)d_in[7];
    float* out = (float*)d_out;

    cudaFuncSetAttribute(rnn_persist, cudaFuncAttributeMaxDynamicSharedMemorySize,
                         SM_FLOATS * (int)sizeof(float));

    inp_kernel<<<dim3(R_, T_), 256>>>(x, W_ih, bias);     // resets g_arrive

    // barriers before launch L: L0=0, L1=62, L2=125, L3=188
    unsigned bars0[4] = {0u, 62u, 125u, 188u};
    for (int L = 0; L < 4; L++){
        rnn_persist<<<R_, 512, SM_FLOATS * sizeof(float)>>>(
            W_hh, W_rhh, C, L*32, L*32 + 32, bars0[L]);
    }

    out_kernel<<<dim3(T_, 2), 128>>>(W_out, b_out, out);
}